// round 7
// baseline (speedup 1.0000x reference)
#include <cuda_runtime.h>
#include <cuda_bf16.h>

// LengthRegulator: out[b,t,:] = x[b, searchsorted(cumsum(dur[b]), t, 'right'), :]
// zeroed where t >= total[b]. mel_mask appended to d_out as float 0/1.

#define BB 32
#define NN 1024
#define DD 384
#define ML 4096
#define D4 (DD / 4)           // 96 float4 per row
#define NROWS (BB * ML)       // 131072 output rows
#define ROWS_PER_WARP 4
#define K2_BLOCK 256

__device__ int g_cum[BB * NN];
__device__ int g_total[BB];
__device__ int g_meta[NROWS];   // src offset in float4 units, or -1 if masked

// ---- K1a: per-batch inclusive scan of durations -> g_cum, g_total ----
__global__ void __launch_bounds__(NN) scan_kernel(const int* __restrict__ dur) {
    const int b = blockIdx.x;
    const int t = threadIdx.x;
    const int lane = t & 31;
    const int w    = t >> 5;

    __shared__ int wsum[32];

    int val = dur[b * NN + t];

    #pragma unroll
    for (int o = 1; o < 32; o <<= 1) {
        int n = __shfl_up_sync(0xFFFFFFFFu, val, o);
        if (lane >= o) val += n;
    }
    if (lane == 31) wsum[w] = val;
    __syncthreads();
    if (w == 0) {
        int s = wsum[lane];
        #pragma unroll
        for (int o = 1; o < 32; o <<= 1) {
            int n = __shfl_up_sync(0xFFFFFFFFu, s, o);
            if (lane >= o) s += n;
        }
        wsum[lane] = s;
    }
    __syncthreads();
    int cum = val + ((w > 0) ? wsum[w - 1] : 0);
    g_cum[b * NN + t] = cum;
    if (t == NN - 1) g_total[b] = cum;
}

// ---- K1b: searches -> g_meta + mask. 8 blocks per batch, 256 threads each ----
#define SEGS 8
#define SEG_T (ML / SEGS)     // 512 rows per block
__global__ void __launch_bounds__(256) search_kernel(
    float* __restrict__ mask_out,
    int write_mask
) {
    const int b   = blockIdx.x >> 3;
    const int seg = blockIdx.x & 7;

    __shared__ int s_cum[NN];
    // cooperative load of the batch's cum (1024 ints via int4)
    ((int4*)s_cum)[threadIdx.x] = ((const int4*)(g_cum + b * NN))[threadIdx.x];
    __syncthreads();

    const int total = s_cum[NN - 1];

    #pragma unroll
    for (int k = 0; k < SEG_T / 256; k++) {
        const int tt = seg * SEG_T + k * 256 + threadIdx.x;
        // branch-free lower bound: pos = #elements <= tt
        int pos = 0;
        #pragma unroll
        for (int step = NN >> 1; step >= 1; step >>= 1) {
            int np = pos + step;
            if (s_cum[np - 1] <= tt) pos = np;
        }
        const int masked = (tt >= total);
        const int idx = pos < (NN - 1) ? pos : (NN - 1);
        g_meta[b * ML + tt] = masked ? -1 : (b * NN + idx) * D4;
        if (write_mask) mask_out[b * ML + tt] = (float)masked;
    }
}

// ---- K2: pure copy. Warp handles 4 rows, 3 float4 per lane per row (MLP 12).
// Streaming stores: out is write-once, keep L2 for x reuse. ----
__global__ void __launch_bounds__(K2_BLOCK) copy_kernel(
    const float4* __restrict__ x4,
    float4* __restrict__ out4
) {
    const int gw   = (blockIdx.x * K2_BLOCK + threadIdx.x) >> 5;
    const int lane = threadIdx.x & 31;
    const int row0 = gw * ROWS_PER_WARP;

    int m[ROWS_PER_WARP];
    #pragma unroll
    for (int r = 0; r < ROWS_PER_WARP; r++) m[r] = __ldg(&g_meta[row0 + r]);

    const float4 z = make_float4(0.f, 0.f, 0.f, 0.f);
    float4 v[ROWS_PER_WARP * 3];

    #pragma unroll
    for (int r = 0; r < ROWS_PER_WARP; r++) {
        if (m[r] >= 0) {
            v[r * 3 + 0] = x4[m[r] + lane];
            v[r * 3 + 1] = x4[m[r] + lane + 32];
            v[r * 3 + 2] = x4[m[r] + lane + 64];
        } else {
            v[r * 3 + 0] = z; v[r * 3 + 1] = z; v[r * 3 + 2] = z;
        }
    }

    float4* d = out4 + (size_t)row0 * D4;
    #pragma unroll
    for (int r = 0; r < ROWS_PER_WARP; r++) {
        __stcs(d + lane,      v[r * 3 + 0]);
        __stcs(d + lane + 32, v[r * 3 + 1]);
        __stcs(d + lane + 64, v[r * 3 + 2]);
        d += D4;
    }
}

extern "C" void kernel_launch(void* const* d_in, const int* in_sizes, int n_in,
                              void* d_out, int out_size) {
    const float* x   = (const float*)d_in[0];
    const int*   dur = (const int*)d_in[1];
    float*       out = (float*)d_out;

    const long long out_elems  = (long long)NROWS * DD;
    const long long mask_elems = (long long)NROWS;
    int write_mask = ((long long)out_size >= out_elems + mask_elems) ? 1 : 0;
    float* mask_out = write_mask ? (out + out_elems) : nullptr;

    scan_kernel<<<BB, NN>>>(dur);
    search_kernel<<<BB * SEGS, 256>>>(mask_out, write_mask);

    const int warps  = NROWS / ROWS_PER_WARP;            // 32768
    const int blocks = warps * 32 / K2_BLOCK;            // 4096
    copy_kernel<<<blocks, K2_BLOCK>>>((const float4*)x, (float4*)out);
}

// round 9
// speedup vs baseline: 1.0719x; 1.0719x over previous
#include <cuda_runtime.h>
#include <cuda_bf16.h>

// LengthRegulator, fully fused single kernel:
// out[b,t,:] = x[b, searchsorted(cumsum(dur[b]), t, 'right'), :], zeroed where
// t >= total[b]. mel_mask appended to d_out as float 0/1.
//
// Each block redundantly scans its batch's 1024 durations (4KB, L2-resident),
// searches for its own 32 output rows, then streams the copy.

#define BB 32
#define NN 1024
#define DD 384
#define ML 4096
#define D4 (DD / 4)            // 96 float4 per row
#define NROWS (BB * ML)        // 131072 output rows
#define TPB 256
#define ROWS_PB 32             // rows per block (8 warps x 4 rows)
#define BPB (ML / ROWS_PB)     // 128 blocks per batch

__global__ void __launch_bounds__(TPB) fused_kernel(
    const float4* __restrict__ x4,
    float4* __restrict__ out4,
    const int* __restrict__ dur,
    float* __restrict__ mask_out,
    int write_mask
) {
    const int b    = blockIdx.x >> 7;       // / BPB
    const int seg  = blockIdx.x & (BPB - 1);
    const int tid  = threadIdx.x;
    const int lane = tid & 31;
    const int w    = tid >> 5;

    __shared__ int s_cum[NN];
    __shared__ int wsum[8];

    // ---- block scan of 1024 durations (4 per thread via int4) ----
    int4 d4 = ((const int4*)(dur + b * NN))[tid];
    const int a0 = d4.x;
    const int a1 = a0 + d4.y;
    const int a2 = a1 + d4.z;
    const int a3 = a2 + d4.w;
    const int tsum = a3;

    int inc = tsum;
    #pragma unroll
    for (int o = 1; o < 32; o <<= 1) {
        int n = __shfl_up_sync(0xFFFFFFFFu, inc, o);
        if (lane >= o) inc += n;
    }
    if (lane == 31) wsum[w] = inc;
    __syncthreads();

    int woff = 0;
    #pragma unroll
    for (int i = 0; i < 8; i++) {
        int wv = wsum[i];
        woff += (i < w) ? wv : 0;
    }
    const int base = woff + (inc - tsum);   // exclusive prefix for this thread

    s_cum[4 * tid + 0] = base + a0;
    s_cum[4 * tid + 1] = base + a1;
    s_cum[4 * tid + 2] = base + a2;
    s_cum[4 * tid + 3] = base + a3;
    __syncthreads();

    const int total = s_cum[NN - 1];

    // ---- searches: warp w owns rows tloc0..tloc0+3; lane computes for (lane&3) ----
    const int tloc0 = seg * ROWS_PB + w * 4;
    const int tt = tloc0 + (lane & 3);

    int pos = 0;
    #pragma unroll
    for (int step = NN >> 1; step >= 1; step >>= 1) {
        int np = pos + step;
        if (s_cum[np - 1] <= tt) pos = np;
    }
    const int idx = pos < (NN - 1) ? pos : (NN - 1);
    const int meta_mine = (tt >= total) ? -1 : (b * NN + idx) * D4;

    int m[4];
    #pragma unroll
    for (int r = 0; r < 4; r++) m[r] = __shfl_sync(0xFFFFFFFFu, meta_mine, r);

    // ---- mask: threads 0..31 write this block's 32 mask values ----
    if (write_mask && tid < ROWS_PB) {
        const int tm = seg * ROWS_PB + tid;
        mask_out[b * ML + tm] = (float)(tm >= total);
    }

    // ---- copy: 4 rows per warp, 3 float4 per lane per row, loads before stores ----
    const float4 z = make_float4(0.f, 0.f, 0.f, 0.f);
    float4 v[12];
    #pragma unroll
    for (int r = 0; r < 4; r++) {
        if (m[r] >= 0) {
            v[r * 3 + 0] = x4[m[r] + lane];
            v[r * 3 + 1] = x4[m[r] + lane + 32];
            v[r * 3 + 2] = x4[m[r] + lane + 64];
        } else {
            v[r * 3 + 0] = z; v[r * 3 + 1] = z; v[r * 3 + 2] = z;
        }
    }

    float4* d = out4 + ((size_t)b * ML + tloc0) * D4;
    #pragma unroll
    for (int r = 0; r < 4; r++) {
        __stcs(d + lane,      v[r * 3 + 0]);
        __stcs(d + lane + 32, v[r * 3 + 1]);
        __stcs(d + lane + 64, v[r * 3 + 2]);
        d += D4;
    }
}

extern "C" void kernel_launch(void* const* d_in, const int* in_sizes, int n_in,
                              void* d_out, int out_size) {
    const float* x   = (const float*)d_in[0];
    const int*   dur = (const int*)d_in[1];
    float*       out = (float*)d_out;

    const long long out_elems  = (long long)NROWS * DD;
    const long long mask_elems = (long long)NROWS;
    int write_mask = ((long long)out_size >= out_elems + mask_elems) ? 1 : 0;
    float* mask_out = write_mask ? (out + out_elems) : nullptr;

    fused_kernel<<<BB * BPB, TPB>>>((const float4*)x, (float4*)out, dur,
                                    mask_out, write_mask);
}